// round 2
// baseline (speedup 1.0000x reference)
#include <cuda_runtime.h>
#include <math.h>
#include <stdint.h>

// Problem constants (fixed shapes for this problem)
#define NN 10000
#define EE 160000
#define CC 128
#define EPW 4

// ---------------- scratch (device globals; no allocation allowed) -------------
__device__ float4 g_h4  [NN*CC/4];        // h = node_feats @ W_up            [N,128]
__device__ float4 g_z4  [EE*64/4];        // radial hidden                    [E,64]
__device__ float4 g_agg4[9*NN*CC/4];      // scattered messages, comp-major   [9][N][128]
__device__ float4 g_svt4[9*NN*CC/4];      // s,v(3),t(5)                      [9][N][128]
__device__ float4 g_B4  [4*NN*CC/4];      // B0, B1x,B1y,B1z                  [4][N][128]
__device__ float4 g_h04 [NN*CC/4];        // h0                               [N,128]
__device__ float4 g_h14 [3*NN*CC/4];      // h1 comp-major                    [3][N][128]
__device__ float4 g_zr4 [NN*64/4];        // readout hidden                   [N,64]

// ---------------- small helpers ----------------
__device__ __forceinline__ void red4(float* p, float a, float b, float c, float d) {
    asm volatile("red.global.add.v4.f32 [%0], {%1,%2,%3,%4};"
                 :: "l"(p), "f"(a), "f"(b), "f"(c), "f"(d) : "memory");
}

__global__ void zero_agg_k(int n4) {
    int i = blockIdx.x * blockDim.x + threadIdx.x;
    if (i < n4) g_agg4[i] = make_float4(0.f, 0.f, 0.f, 0.f);
}

// ---------------- generic fp32 GEMM: C = act(A@B + bias + ecol*erow) ----------
// 64x64 tile, BK=16, 256 threads, 4x4 per thread. Requires K % 16 == 0.
template<int ACT>
__global__ void __launch_bounds__(256)
gemm_k(const float* __restrict__ A, const float* __restrict__ B,
       float* __restrict__ C, int M, int N, int K,
       const float* __restrict__ bias,
       const float* __restrict__ ecol, const float* __restrict__ erow)
{
    __shared__ float As[16][68];
    __shared__ float Bs[16][64];
    int tid = threadIdx.x;
    int tx = tid & 15, ty = tid >> 4;
    int bm = blockIdx.y * 64, bn = blockIdx.x * 64;

    float acc[4][4];
#pragma unroll
    for (int i = 0; i < 4; i++)
#pragma unroll
        for (int j = 0; j < 4; j++) acc[i][j] = 0.f;

    int mi = tid >> 2;   // 0..63
    int kq = tid & 3;    // which float4 of the 16-wide K slab
    bool mvalid = (bm + mi) < M;
    const float* Arow = A + (size_t)(bm + mi) * K;

    for (int k0 = 0; k0 < K; k0 += 16) {
        float4 av = make_float4(0.f, 0.f, 0.f, 0.f);
        if (mvalid) av = *(const float4*)(Arow + k0 + kq * 4);
        As[kq*4+0][mi] = av.x;
        As[kq*4+1][mi] = av.y;
        As[kq*4+2][mi] = av.z;
        As[kq*4+3][mi] = av.w;
#pragma unroll
        for (int l = 0; l < 4; l++) {
            int idx = tid + l * 256;
            int ki = idx >> 6, ni = idx & 63;
            int n = bn + ni;
            Bs[ki][ni] = (n < N) ? B[(size_t)(k0 + ki) * N + n] : 0.f;
        }
        __syncthreads();
#pragma unroll
        for (int kk = 0; kk < 16; kk++) {
            float4 a4 = *(const float4*)(&As[kk][ty * 4]);
            float4 b4 = *(const float4*)(&Bs[kk][tx * 4]);
            float a[4] = {a4.x, a4.y, a4.z, a4.w};
            float b[4] = {b4.x, b4.y, b4.z, b4.w};
#pragma unroll
            for (int i = 0; i < 4; i++)
#pragma unroll
                for (int j = 0; j < 4; j++)
                    acc[i][j] = fmaf(a[i], b[j], acc[i][j]);
        }
        __syncthreads();
    }
#pragma unroll
    for (int i = 0; i < 4; i++) {
        int m = bm + ty * 4 + i;
        if (m >= M) continue;
        float ec = ecol ? ecol[m] : 0.f;
#pragma unroll
        for (int j = 0; j < 4; j++) {
            int n = bn + tx * 4 + j;
            if (n >= N) continue;
            float v = acc[i][j];
            if (bias) v += bias[n];
            if (ecol) v = fmaf(ec, erow[n], v);
            if (ACT)  v = v / (1.f + __expf(-v));
            C[(size_t)m * N + n] = v;
        }
    }
}

// ---------------- edge kernel: R = z@Wr2 (smem), messages, scatter -----------
__global__ void __launch_bounds__(256)
edge_kernel(const float* __restrict__ vectors,
            const int*   __restrict__ edge_index,
            const float* __restrict__ Wr2,
            int E, int N)
{
    extern __shared__ float sm[];
    float* wsm = sm;  // Wr2: 64*384 floats
    int lane = threadIdx.x & 31, wid = threadIdx.x >> 5;
    float* zsh = sm + 64 * 384 + wid * (EPW * 64);

    for (int i = threadIdx.x; i < 64 * 384; i += blockDim.x) wsm[i] = Wr2[i];
    __syncthreads();

    const float4* w4  = (const float4*)wsm;   // 96 float4 per k-row
    const float*  zg  = (const float*)g_z4;
    const float4* h4  = (const float4*)g_h4;
    float*        agg = (float*)g_agg4;
    int NC = N * CC;

    int gw = blockIdx.x * (blockDim.x >> 5) + wid;
    int nw = gridDim.x * (blockDim.x >> 5);
    int ngroups = (E + EPW - 1) / EPW;

    for (int g = gw; g < ngroups; g += nw) {
        int e0 = g * EPW;
        int cnt = E - e0; if (cnt > EPW) cnt = EPW;
        for (int j = 0; j < cnt; j++) {
            zsh[j * 64 + lane]      = zg[(size_t)(e0 + j) * 64 + lane];
            zsh[j * 64 + lane + 32] = zg[(size_t)(e0 + j) * 64 + lane + 32];
        }
        __syncwarp();

        float4 acc[EPW][3];
#pragma unroll
        for (int j = 0; j < EPW; j++)
#pragma unroll
            for (int p = 0; p < 3; p++) acc[j][p] = make_float4(0.f, 0.f, 0.f, 0.f);

#pragma unroll 4
        for (int k = 0; k < 64; k++) {
            float4 b0 = w4[k * 96 +      lane];
            float4 b1 = w4[k * 96 + 32 + lane];
            float4 b2 = w4[k * 96 + 64 + lane];
#pragma unroll
            for (int j = 0; j < EPW; j++) {
                float zk = zsh[j * 64 + k];
                acc[j][0].x = fmaf(zk, b0.x, acc[j][0].x);
                acc[j][0].y = fmaf(zk, b0.y, acc[j][0].y);
                acc[j][0].z = fmaf(zk, b0.z, acc[j][0].z);
                acc[j][0].w = fmaf(zk, b0.w, acc[j][0].w);
                acc[j][1].x = fmaf(zk, b1.x, acc[j][1].x);
                acc[j][1].y = fmaf(zk, b1.y, acc[j][1].y);
                acc[j][1].z = fmaf(zk, b1.z, acc[j][1].z);
                acc[j][1].w = fmaf(zk, b1.w, acc[j][1].w);
                acc[j][2].x = fmaf(zk, b2.x, acc[j][2].x);
                acc[j][2].y = fmaf(zk, b2.y, acc[j][2].y);
                acc[j][2].z = fmaf(zk, b2.z, acc[j][2].z);
                acc[j][2].w = fmaf(zk, b2.w, acc[j][2].w);
            }
        }

        for (int j = 0; j < cnt; j++) {
            int e = e0 + j;
            int snd = edge_index[e];
            int rcv = edge_index[E + e];
            float4 hs = h4[(size_t)snd * 32 + lane];

            float vx = vectors[3 * e], vy = vectors[3 * e + 1], vz = vectors[3 * e + 2];
            float nrm = sqrtf(fmaf(vx, vx, fmaf(vy, vy, vz * vz)));
            float inv = 1.f / (nrm + 1e-9f);
            float ux = vx * inv, uy = vy * inv, uz = vz * inv;
            const float s3   = 1.7320508075688772f;
            const float s15  = 3.8729833462074170f;
            const float s15h = 1.9364916731037085f;
            const float s5h  = 1.1180339887498949f;
            float Y1x = s3 * ux, Y1y = s3 * uy, Y1z = s3 * uz;
            float Y2a = s15 * ux * uy;
            float Y2b = s15 * uy * uz;
            float Y2c = s5h * (3.f * uz * uz - 1.f);
            float Y2d = s15 * ux * uz;
            float Y2e = s15h * (ux * ux - uy * uy);

            const float ia = 0.0625f;  // fold 1/AVG into coefficients
            float c0x = hs.x * acc[j][0].x * ia, c0y = hs.y * acc[j][0].y * ia,
                  c0z = hs.z * acc[j][0].z * ia, c0w = hs.w * acc[j][0].w * ia;
            float c1x = hs.x * acc[j][1].x * ia, c1y = hs.y * acc[j][1].y * ia,
                  c1z = hs.z * acc[j][1].z * ia, c1w = hs.w * acc[j][1].w * ia;
            float c2x = hs.x * acc[j][2].x * ia, c2y = hs.y * acc[j][2].y * ia,
                  c2z = hs.z * acc[j][2].z * ia, c2w = hs.w * acc[j][2].w * ia;

            float* base = agg + (size_t)rcv * CC + lane * 4;
            red4(base,            c0x,       c0y,       c0z,       c0w);
            red4(base + 1 * NC,   c1x * Y1x, c1y * Y1x, c1z * Y1x, c1w * Y1x);
            red4(base + 2 * NC,   c1x * Y1y, c1y * Y1y, c1z * Y1y, c1w * Y1y);
            red4(base + 3 * NC,   c1x * Y1z, c1y * Y1z, c1z * Y1z, c1w * Y1z);
            red4(base + 4 * NC,   c2x * Y2a, c2y * Y2a, c2z * Y2a, c2w * Y2a);
            red4(base + 5 * NC,   c2x * Y2b, c2y * Y2b, c2z * Y2b, c2w * Y2b);
            red4(base + 6 * NC,   c2x * Y2c, c2y * Y2c, c2z * Y2c, c2w * Y2c);
            red4(base + 7 * NC,   c2x * Y2d, c2y * Y2d, c2z * Y2d, c2w * Y2d);
            red4(base + 8 * NC,   c2x * Y2e, c2y * Y2e, c2z * Y2e, c2w * Y2e);
        }
        __syncwarp();
    }
}

// ---------------- symmetric contraction (elementwise over n,c) ---------------
__global__ void contract_k(const float* __restrict__ w0, const float* __restrict__ w1, int N)
{
    int i = blockIdx.x * blockDim.x + threadIdx.x;
    int NC = N * CC;
    if (i >= NC) return;
    int c = i & (CC - 1);
    const float* svt = (const float*)g_svt4;
    float* Bv = (float*)g_B4;

    float s  = svt[i];
    float vx = svt[NC + i], vy = svt[2 * NC + i], vz = svt[3 * NC + i];
    float ta = svt[4 * NC + i], tb = svt[5 * NC + i], tcm = svt[6 * NC + i];
    float td = svt[7 * NC + i], te = svt[8 * NC + i];

    float c3 = tcm * 0.5773502691896258f;  // c / sqrt(3)
    float Txx = te - c3, Txy = ta, Txz = td;
    float Tyy = -te - c3, Tyz = tb;
    float Tzz = 2.f * c3;

    float v2 = vx * vx + vy * vy + vz * vz;
    float t2 = ta * ta + tb * tb + tcm * tcm + td * td + te * te;
    float Tvx = Txx * vx + Txy * vy + Txz * vz;
    float Tvy = Txy * vx + Tyy * vy + Tyz * vz;
    float Tvz = Txz * vx + Tyz * vy + Tzz * vz;
    float vTv = vx * Tvx + vy * Tvy + vz * Tvz;

    float B0 = w0[c] * s + w0[CC + c] * s * s + w0[2 * CC + c] * v2 + w0[3 * CC + c] * t2
             + w0[4 * CC + c] * s * s * s + w0[5 * CC + c] * s * v2
             + w0[6 * CC + c] * s * t2 + w0[7 * CC + c] * vTv;

    float k0 = w1[c], k1 = w1[CC + c], k2 = w1[2 * CC + c];
    float k3 = w1[3 * CC + c], k4 = w1[4 * CC + c], k5 = w1[5 * CC + c];
    float f = k0 + k1 * s + k3 * s * s + k4 * v2;   // coefficient on v
    float gT = k2 + k5 * s;                          // coefficient on Tv
    float B1x = f * vx + gT * Tvx;
    float B1y = f * vy + gT * Tvy;
    float B1z = f * vz + gT * Tvz;

    Bv[i] = B0;
    Bv[NC + i] = B1x;
    Bv[2 * NC + i] = B1y;
    Bv[3 * NC + i] = B1z;
}

// ---------------- finalize: gate, vec, node_feats_out ------------------------
__global__ void final_k(const float* __restrict__ W3, const float* __restrict__ wv,
                        float* __restrict__ out, int N)
{
    int lane = threadIdx.x & 31;
    int node = (blockIdx.x * blockDim.x + threadIdx.x) >> 5;
    if (node >= N) return;
    int NC = N * CC;
    const float* zr = (const float*)g_zr4;
    const float* h0 = (const float*)g_h04;
    const float* h1 = (const float*)g_h14;

    float gate = zr[node * 64 + lane] * W3[lane] + zr[node * 64 + 32 + lane] * W3[32 + lane];
    float sx = 0.f, sy = 0.f, sz = 0.f;
#pragma unroll
    for (int c = lane; c < CC; c += 32) {
        float w = wv[c];
        sx = fmaf(h1[node * CC + c], w, sx);
        sy = fmaf(h1[NC + node * CC + c], w, sy);
        sz = fmaf(h1[2 * NC + node * CC + c], w, sz);
    }
#pragma unroll
    for (int off = 16; off; off >>= 1) {
        gate += __shfl_xor_sync(0xffffffffu, gate, off);
        sx   += __shfl_xor_sync(0xffffffffu, sx, off);
        sy   += __shfl_xor_sync(0xffffffffu, sy, off);
        sz   += __shfl_xor_sync(0xffffffffu, sz, off);
    }
    if (lane == 0) {
        float* ov = out + (size_t)N * 128 + (size_t)node * 3;
        ov[0] = sx * gate;
        ov[1] = sy * gate;
        ov[2] = sz * gate;
    }
    float* nf = out + (size_t)N * 131 + (size_t)node * 512;
#pragma unroll
    for (int c = lane; c < CC; c += 32) {
        nf[c] = h0[node * CC + c];
        nf[128 + 3 * c + 0] = h1[node * CC + c];
        nf[128 + 3 * c + 1] = h1[NC + node * CC + c];
        nf[128 + 3 * c + 2] = h1[2 * NC + node * CC + c];
    }
}

// ---------------- host launcher ----------------------------------------------
extern "C" void kernel_launch(void* const* d_in, const int* in_sizes, int n_in,
                              void* d_out, int out_size)
{
    const float* vectors    = (const float*)d_in[0];
    const float* lengths    = (const float*)d_in[1];
    const float* node_feats = (const float*)d_in[2];
    const float* edge_feats = (const float*)d_in[3];
    const int*   edge_index = (const int*)  d_in[4];
    const float* W_up = (const float*)d_in[5];
    const float* Wr1  = (const float*)d_in[6];
    const float* br1  = (const float*)d_in[7];
    const float* Wr2  = (const float*)d_in[8];
    const float* Wl0  = (const float*)d_in[9];
    const float* Wl1  = (const float*)d_in[10];
    const float* Wl2  = (const float*)d_in[11];
    const float* w0   = (const float*)d_in[12];
    const float* w1   = (const float*)d_in[13];
    const float* P0   = (const float*)d_in[14];
    const float* P1   = (const float*)d_in[15];
    const float* W1   = (const float*)d_in[16];
    const float* b1   = (const float*)d_in[17];
    const float* W2   = (const float*)d_in[18];
    const float* W3   = (const float*)d_in[19];
    const float* wv   = (const float*)d_in[20];
    float* out = (float*)d_out;

    int E = in_sizes[1];           // lengths is [E,1]
    int N = in_sizes[2] / CC;      // node_feats is [N,128]
    int NC = N * CC;

    float *p_h, *p_z, *p_agg, *p_svt, *p_B, *p_h0, *p_h1, *p_zr;
    cudaGetSymbolAddress((void**)&p_h,   g_h4);
    cudaGetSymbolAddress((void**)&p_z,   g_z4);
    cudaGetSymbolAddress((void**)&p_agg, g_agg4);
    cudaGetSymbolAddress((void**)&p_svt, g_svt4);
    cudaGetSymbolAddress((void**)&p_B,   g_B4);
    cudaGetSymbolAddress((void**)&p_h0,  g_h04);
    cudaGetSymbolAddress((void**)&p_h1,  g_h14);
    cudaGetSymbolAddress((void**)&p_zr,  g_zr4);

    // 0) zero the scatter accumulators
    int n4 = 9 * NC / 4;
    zero_agg_k<<<(n4 + 255) / 256, 256>>>(n4);

    // 1) h = node_feats @ W_up   [N,128]
    gemm_k<0><<<dim3(2, (N + 63) / 64), 256>>>(node_feats, W_up, p_h, N, 128, 128,
                                               nullptr, nullptr, nullptr);

    // 2) z = silu(edge_feats @ Wr1[:128] + lengths * Wr1[128] + br1)   [E,64]
    gemm_k<1><<<dim3(1, (E + 63) / 64), 256>>>(edge_feats, Wr1, p_z, E, 64, 128,
                                               br1, lengths, Wr1 + 128 * 64);

    // 3) edge kernel: R = z@Wr2 (smem), messages, vector red into agg
    int smem_bytes = (64 * 384 + 8 * EPW * 64) * 4;
    cudaFuncSetAttribute(edge_kernel, cudaFuncAttributeMaxDynamicSharedMemorySize, smem_bytes);
    edge_kernel<<<296, 256, smem_bytes>>>(vectors, edge_index, Wr2, E, N);

    // 4) s,v,t: 9 GEMMs [N,128]@[128,128]
    dim3 gn(2, (N + 63) / 64);
    gemm_k<0><<<gn, 256>>>(p_agg, Wl0, p_svt, N, 128, 128, nullptr, nullptr, nullptr);
    for (int x = 0; x < 3; x++)
        gemm_k<0><<<gn, 256>>>(p_agg + (size_t)(1 + x) * NC, Wl1,
                               p_svt + (size_t)(1 + x) * NC, N, 128, 128,
                               nullptr, nullptr, nullptr);
    for (int x = 0; x < 5; x++)
        gemm_k<0><<<gn, 256>>>(p_agg + (size_t)(4 + x) * NC, Wl2,
                               p_svt + (size_t)(4 + x) * NC, N, 128, 128,
                               nullptr, nullptr, nullptr);

    // 5) symmetric contraction -> B0, B1
    contract_k<<<(NC + 255) / 256, 256>>>(w0, w1, N);

    // 6) h0 = B0@P0, h1x = B1x@P1
    gemm_k<0><<<gn, 256>>>(p_B, P0, p_h0, N, 128, 128, nullptr, nullptr, nullptr);
    for (int x = 0; x < 3; x++)
        gemm_k<0><<<gn, 256>>>(p_B + (size_t)(1 + x) * NC, P1,
                               p_h1 + (size_t)x * NC, N, 128, 128,
                               nullptr, nullptr, nullptr);

    // 7) zr = silu(h0@W1 + b1)
    gemm_k<1><<<dim3(1, (N + 63) / 64), 256>>>(p_h0, W1, p_zr, N, 64, 128,
                                               b1, nullptr, nullptr);

    // 8) scal = zr@W2  -> directly into d_out[0 : N*128]
    gemm_k<0><<<dim3(2, (N + 63) / 64), 256>>>(p_zr, W2, out, N, 128, 64,
                                               nullptr, nullptr, nullptr);

    // 9) gate, vec, node_feats_out
    final_k<<<(N * 32 + 255) / 256, 256>>>(W3, wv, out, N);
}

// round 4
// speedup vs baseline: 1.1106x; 1.1106x over previous
#include <cuda_runtime.h>
#include <cuda_fp16.h>
#include <math.h>
#include <stdint.h>

#define NN 10000
#define EE 160000
#define CC 128

// ---------------- scratch ------------------------------------------------------
__device__ float  g_h   [NN*CC];
__device__ __half g_zhi [EE*64];
__device__ __half g_zlo [EE*64];
__device__ float  g_agg [9*NN*CC];
__device__ float  g_svt [9*NN*CC];
__device__ float  g_B   [4*NN*CC];
__device__ float  g_hout[4*NN*CC];          // h0, h1x, h1y, h1z
__device__ float  g_zr  [NN*64];
// prepped weights: f16 hi then lo, [n][k] rows padded
__device__ __half g_wt  [6*2*128*136];      // 0 W_up, 1 Wl0, 2 Wl1, 3 Wl2, 4 P0, 5 P1 (stride 136)
__device__ __half g_wr1t[2*64*136];         // Wr1^T   (stride 136)
__device__ __half g_wr2t[2*384*72];         // Wr2^T   (stride 72)

// ---------------- helpers -------------------------------------------------------
__device__ __forceinline__ uint32_t s2u(const void* p) {
    uint32_t a;
    asm("{ .reg .u64 t; cvta.to.shared.u64 t, %1; cvt.u32.u64 %0, t; }" : "=r"(a) : "l"(p));
    return a;
}
__device__ __forceinline__ void ldmx4(uint32_t& r0, uint32_t& r1, uint32_t& r2, uint32_t& r3,
                                      uint32_t a) {
    asm volatile("ldmatrix.sync.aligned.m8n8.x4.shared.b16 {%0,%1,%2,%3}, [%4];"
                 : "=r"(r0), "=r"(r1), "=r"(r2), "=r"(r3) : "r"(a));
}
__device__ __forceinline__ void mma4(float c[4], uint32_t a0, uint32_t a1, uint32_t a2,
                                     uint32_t a3, uint32_t b0, uint32_t b1) {
    asm volatile("mma.sync.aligned.m16n8k16.row.col.f32.f16.f16.f32 "
                 "{%0,%1,%2,%3},{%4,%5,%6,%7},{%8,%9},{%0,%1,%2,%3};"
                 : "+f"(c[0]), "+f"(c[1]), "+f"(c[2]), "+f"(c[3])
                 : "r"(a0), "r"(a1), "r"(a2), "r"(a3), "r"(b0), "r"(b1));
}
// A fragment: rows mrow.., k-slab kb (16 wide)
__device__ __forceinline__ uint32_t afa(uint32_t base, int lane, int mrow, int kb, int sh) {
    int row = mrow + (lane & 15);
    int k = kb + ((lane >> 4) << 3);
    return base + (uint32_t)(row * sh + k) * 2;
}
// B fragment pair (two n8 tiles at nb): B stored [n][k]
__device__ __forceinline__ uint32_t bfa(uint32_t base, int lane, int nb, int kb, int sh) {
    int n = nb + (lane & 7) + ((lane >> 4) << 3);
    int k = kb + (((lane >> 3) & 1) << 3);
    return base + (uint32_t)(n * sh + k) * 2;
}
__device__ __forceinline__ void red4(float* p, float a, float b, float c, float d) {
    asm volatile("red.global.add.v4.f32 [%0], {%1,%2,%3,%4};"
                 :: "l"(p), "f"(a), "f"(b), "f"(c), "f"(d) : "memory");
}

// ---------------- weight prep: dst[n][k] = W[k][n], hi then lo ------------------
__global__ void prep_w(const float* __restrict__ W, __half* __restrict__ dst,
                       int K, int Nr, int ldw, int stride) {
    int i = blockIdx.x * blockDim.x + threadIdx.x;
    if (i >= K * Nr) return;
    int n = i / K, k = i % K;
    float v = W[(size_t)k * ldw + n];
    __half h = __float2half_rn(v);
    dst[(size_t)n * stride + k] = h;
    dst[(size_t)Nr * stride + (size_t)n * stride + k] = __float2half_rn(v - __half2float(h));
}

__global__ void zero_agg_k(int n4) {
    int i = blockIdx.x * blockDim.x + threadIdx.x;
    if (i < n4) ((float4*)g_agg)[i] = make_float4(0.f, 0.f, 0.f, 0.f);
}

// A-tile convert: fp32 row -> hi/lo f16 in smem (stride 136)
__device__ __forceinline__ void cvt_row(__half* Ah, __half* Al, int r, int half64,
                                        const float* Arow, bool valid) {
    int cb = half64 * 64;
#pragma unroll
    for (int q = 0; q < 16; q++) {
        float4 v = valid ? ((const float4*)Arow)[half64 * 16 + q]
                         : make_float4(0.f, 0.f, 0.f, 0.f);
        int idx = r * 136 + cb + q * 4;
        __half h0 = __float2half_rn(v.x), h1 = __float2half_rn(v.y);
        __half h2 = __float2half_rn(v.z), h3 = __float2half_rn(v.w);
        ((__half2*)(Ah + idx))[0] = __halves2half2(h0, h1);
        ((__half2*)(Ah + idx))[1] = __halves2half2(h2, h3);
        ((__half2*)(Al + idx))[0] = __halves2half2(__float2half_rn(v.x - __half2float(h0)),
                                                   __float2half_rn(v.y - __half2float(h1)));
        ((__half2*)(Al + idx))[1] = __halves2half2(__float2half_rn(v.z - __half2float(h2)),
                                                   __float2half_rn(v.w - __half2float(h3)));
    }
}

// ---------------- node GEMM: O[128-tile,128] = A @ tile(W) ----------------------
// smem: Ah(0) Al(17408) Bh(34816) Bl(52224), halves; total 139264 B
__global__ void __launch_bounds__(256)
mma128(const float* __restrict__ A0, float* __restrict__ O0, int M, int phase)
{
    extern __shared__ __half sh[];
    __half* Ah = sh;  __half* Al = sh + 17408;
    __half* Bh = sh + 34816;
    uint32_t sb = s2u(sh);
    int tid = threadIdx.x, wid = tid >> 5, lane = tid & 31;
    int comp = blockIdx.y;
    int bm = blockIdx.x * 128;
    int tile;
    if (phase == 0) tile = 0;
    else if (phase == 1) tile = (comp == 0) ? 1 : (comp < 4 ? 2 : 3);
    else tile = (comp == 0) ? 4 : 5;
    const float* A = A0 + (size_t)comp * M * 128;
    float* O = O0 + (size_t)comp * M * 128;

    {   // B copy: 2*128*136 halves = 4352 uint4
        const uint4* s = (const uint4*)(g_wt + (size_t)tile * (2*128*136));
        uint4* d = (uint4*)Bh;
        for (int i = tid; i < 4352; i += 256) d[i] = s[i];
    }
    {   // A convert: 128 rows, 2 threads/row
        int r = tid >> 1, hf = tid & 1;
        bool valid = (bm + r) < M;
        cvt_row(Ah, Al, r, hf, A + (size_t)(bm + r) * 128, valid);
    }
    __syncthreads();

    uint32_t ab_h = sb, ab_l = sb + 17408*2, bb_h = sb + 34816*2, bb_l = sb + 52224*2;
    int mrow = wid * 16;
    float C[16][4];
#pragma unroll
    for (int i = 0; i < 16; i++)
#pragma unroll
        for (int j = 0; j < 4; j++) C[i][j] = 0.f;

    for (int kb = 0; kb < 128; kb += 16) {
        uint32_t ah0, ah1, ah2, ah3, al0, al1, al2, al3;
        ldmx4(ah0, ah1, ah2, ah3, afa(ab_h, lane, mrow, kb, 136));
        ldmx4(al0, al1, al2, al3, afa(ab_l, lane, mrow, kb, 136));
#pragma unroll
        for (int nt2 = 0; nt2 < 8; nt2++) {
            uint32_t bh0, bh1, bh2, bh3, bl0, bl1, bl2, bl3;
            ldmx4(bh0, bh1, bh2, bh3, bfa(bb_h, lane, nt2 * 16, kb, 136));
            ldmx4(bl0, bl1, bl2, bl3, bfa(bb_l, lane, nt2 * 16, kb, 136));
            mma4(C[2*nt2],   ah0, ah1, ah2, ah3, bh0, bh1);
            mma4(C[2*nt2],   al0, al1, al2, al3, bh0, bh1);
            mma4(C[2*nt2],   ah0, ah1, ah2, ah3, bl0, bl1);
            mma4(C[2*nt2+1], ah0, ah1, ah2, ah3, bh2, bh3);
            mma4(C[2*nt2+1], al0, al1, al2, al3, bh2, bh3);
            mma4(C[2*nt2+1], ah0, ah1, ah2, ah3, bl2, bl3);
        }
    }

    int r0 = bm + mrow + (lane >> 2);
    int c0 = (lane & 3) * 2;
    bool v0 = r0 < M, v1 = (r0 + 8) < M;
#pragma unroll
    for (int nt = 0; nt < 16; nt++) {
        int col = nt * 8 + c0;
        if (v0) *(float2*)(O + (size_t)r0 * 128 + col) = make_float2(C[nt][0], C[nt][1]);
        if (v1) *(float2*)(O + (size_t)(r0 + 8) * 128 + col) = make_float2(C[nt][2], C[nt][3]);
    }
}

// ---------------- radial: z = silu(ef@Wr1 + len*wl + b) -> f16 hi/lo ------------
// smem: Ah(0) Al(17408) Bh(34816) Bl(43520) halves, then wl/bias floats
__global__ void __launch_bounds__(256)
mma_radial(const float* __restrict__ A, const float* __restrict__ lengths,
           const float* __restrict__ wlast, const float* __restrict__ bias, int M)
{
    extern __shared__ __half sh[];
    __half* Ah = sh;  __half* Al = sh + 17408;
    __half* Bh = sh + 34816;
    float* wl_sm = (float*)(sh + 52224);
    float* b_sm  = wl_sm + 64;
    uint32_t sb = s2u(sh);
    int tid = threadIdx.x, wid = tid >> 5, lane = tid & 31;
    int bm = blockIdx.x * 128;

    if (tid < 64) { wl_sm[tid] = wlast[tid]; b_sm[tid] = bias[tid]; }
    {   // B copy: 2*64*136 halves = 2176 uint4
        const uint4* s = (const uint4*)g_wr1t;
        uint4* d = (uint4*)Bh;
        for (int i = tid; i < 2176; i += 256) d[i] = s[i];
    }
    {   int r = tid >> 1, hf = tid & 1;
        bool valid = (bm + r) < M;
        cvt_row(Ah, Al, r, hf, A + (size_t)(bm + r) * 128, valid);
    }
    __syncthreads();

    uint32_t ab_h = sb, ab_l = sb + 17408*2, bb_h = sb + 34816*2, bb_l = sb + 43520*2;
    int mrow = wid * 16;
    float C[8][4];
#pragma unroll
    for (int i = 0; i < 8; i++)
#pragma unroll
        for (int j = 0; j < 4; j++) C[i][j] = 0.f;

    for (int kb = 0; kb < 128; kb += 16) {
        uint32_t ah0, ah1, ah2, ah3, al0, al1, al2, al3;
        ldmx4(ah0, ah1, ah2, ah3, afa(ab_h, lane, mrow, kb, 136));
        ldmx4(al0, al1, al2, al3, afa(ab_l, lane, mrow, kb, 136));
#pragma unroll
        for (int nt2 = 0; nt2 < 4; nt2++) {
            uint32_t bh0, bh1, bh2, bh3, bl0, bl1, bl2, bl3;
            ldmx4(bh0, bh1, bh2, bh3, bfa(bb_h, lane, nt2 * 16, kb, 136));
            ldmx4(bl0, bl1, bl2, bl3, bfa(bb_l, lane, nt2 * 16, kb, 136));
            mma4(C[2*nt2],   ah0, ah1, ah2, ah3, bh0, bh1);
            mma4(C[2*nt2],   al0, al1, al2, al3, bh0, bh1);
            mma4(C[2*nt2],   ah0, ah1, ah2, ah3, bl0, bl1);
            mma4(C[2*nt2+1], ah0, ah1, ah2, ah3, bh2, bh3);
            mma4(C[2*nt2+1], al0, al1, al2, al3, bh2, bh3);
            mma4(C[2*nt2+1], ah0, ah1, ah2, ah3, bl2, bl3);
        }
    }

    int r0 = bm + mrow + (lane >> 2);
    int c0 = (lane & 3) * 2;
    bool v0 = r0 < M, v1 = (r0 + 8) < M;
    float len0 = v0 ? lengths[r0] : 0.f;
    float len1 = v1 ? lengths[r0 + 8] : 0.f;
#pragma unroll
    for (int nt = 0; nt < 8; nt++) {
        int col = nt * 8 + c0;
        float wl0 = wl_sm[col], wl1 = wl_sm[col + 1];
        float bb0 = b_sm[col], bb1 = b_sm[col + 1];
        if (v0) {
            float f0 = C[nt][0] + len0 * wl0 + bb0;
            float f1 = C[nt][1] + len0 * wl1 + bb1;
            f0 = f0 / (1.f + __expf(-f0));
            f1 = f1 / (1.f + __expf(-f1));
            __half h0 = __float2half_rn(f0), h1 = __float2half_rn(f1);
            *(__half2*)(g_zhi + (size_t)r0 * 64 + col) = __halves2half2(h0, h1);
            *(__half2*)(g_zlo + (size_t)r0 * 64 + col) =
                __halves2half2(__float2half_rn(f0 - __half2float(h0)),
                               __float2half_rn(f1 - __half2float(h1)));
        }
        if (v1) {
            float f0 = C[nt][2] + len1 * wl0 + bb0;
            float f1 = C[nt][3] + len1 * wl1 + bb1;
            f0 = f0 / (1.f + __expf(-f0));
            f1 = f1 / (1.f + __expf(-f1));
            __half h0 = __float2half_rn(f0), h1 = __float2half_rn(f1);
            *(__half2*)(g_zhi + (size_t)(r0 + 8) * 64 + col) = __halves2half2(h0, h1);
            *(__half2*)(g_zlo + (size_t)(r0 + 8) * 64 + col) =
                __halves2half2(__float2half_rn(f0 - __half2float(h0)),
                               __float2half_rn(f1 - __half2float(h1)));
        }
    }
}

// ---------------- edge: mma R = z@Wr2 (3 chunks of 128 cols) + scatter ----------
// smem bytes: zh 0..18432, zl ..36864, Wh ..92160, Wl ..147456,
//             stage ..215040, Ys ..219136, idx ..220160
__global__ void __launch_bounds__(256)
edge_mma(const float* __restrict__ vectors, const int* __restrict__ edge_index,
         int E, int N)
{
    extern __shared__ char smc[];
    uint32_t sb = s2u(smc);
    float* stage = (float*)(smc + 147456);
    float* Ys    = (float*)(smc + 215040);
    int* snd_s   = (int*)(smc + 219136);
    int* rcv_s   = (int*)(smc + 219136 + 512);
    int tid = threadIdx.x, wid = tid >> 5, lane = tid & 31;
    int e0 = blockIdx.x * 128;

    {   // z copy: 128 rows x 64 halves -> stride 72
        for (int i = tid; i < 1024; i += 256) {
            int row = i >> 3, c8 = i & 7;
            *(uint4*)(smc + row * 144 + c8 * 16) =
                ((const uint4*)(g_zhi + (size_t)(e0 + row) * 64))[c8];
            *(uint4*)(smc + 18432 + row * 144 + c8 * 16) =
                ((const uint4*)(g_zlo + (size_t)(e0 + row) * 64))[c8];
        }
    }
    {   // Wr2 copy: 2*384*72 halves = 6912 uint4
        const uint4* s = (const uint4*)g_wr2t;
        uint4* d = (uint4*)(smc + 36864);
        for (int i = tid; i < 6912; i += 256) d[i] = s[i];
    }
    if (tid < 128) {
        int e = e0 + tid;
        int snd = 0, rcv = 0;
        float vx = 0.f, vy = 1.f, vz = 0.f;
        if (e < E) {
            snd = edge_index[e]; rcv = edge_index[E + e];
            vx = vectors[3*e]; vy = vectors[3*e+1]; vz = vectors[3*e+2];
        }
        snd_s[tid] = snd; rcv_s[tid] = rcv;
        float inv = 1.f / (sqrtf(vx*vx + vy*vy + vz*vz) + 1e-9f);
        float ux = vx*inv, uy = vy*inv, uz = vz*inv;
        const float S3 = 1.7320508075688772f, S15 = 3.8729833462074170f;
        const float S15H = 1.9364916731037085f, S5H = 1.1180339887498949f;
        float* y = Ys + tid * 8;
        y[0] = S3*ux; y[1] = S3*uy; y[2] = S3*uz;
        y[3] = S15*ux*uy; y[4] = S15*uy*uz; y[5] = S5H*(3.f*uz*uz - 1.f);
        y[6] = S15*ux*uz; y[7] = S15H*(ux*ux - uy*uy);
    }
    __syncthreads();

    uint32_t zb_h = sb, zb_l = sb + 18432;
    int mrow = wid * 16;
    const float4* h4g = (const float4*)g_h;
    int NC = N * CC;

    for (int l = 0; l < 3; l++) {
        uint32_t wb_h = sb + 36864 + (uint32_t)l * 18432;
        uint32_t wb_l = sb + 92160 + (uint32_t)l * 18432;
        float C[16][4];
#pragma unroll
        for (int i = 0; i < 16; i++)
#pragma unroll
            for (int j = 0; j < 4; j++) C[i][j] = 0.f;

        for (int kb = 0; kb < 64; kb += 16) {
            uint32_t ah0, ah1, ah2, ah3, al0, al1, al2, al3;
            ldmx4(ah0, ah1, ah2, ah3, afa(zb_h, lane, mrow, kb, 72));
            ldmx4(al0, al1, al2, al3, afa(zb_l, lane, mrow, kb, 72));
#pragma unroll
            for (int nt2 = 0; nt2 < 8; nt2++) {
                uint32_t bh0, bh1, bh2, bh3, bl0, bl1, bl2, bl3;
                ldmx4(bh0, bh1, bh2, bh3, bfa(wb_h, lane, nt2 * 16, kb, 72));
                ldmx4(bl0, bl1, bl2, bl3, bfa(wb_l, lane, nt2 * 16, kb, 72));
                mma4(C[2*nt2],   ah0, ah1, ah2, ah3, bh0, bh1);
                mma4(C[2*nt2],   al0, al1, al2, al3, bh0, bh1);
                mma4(C[2*nt2],   ah0, ah1, ah2, ah3, bl0, bl1);
                mma4(C[2*nt2+1], ah0, ah1, ah2, ah3, bh2, bh3);
                mma4(C[2*nt2+1], al0, al1, al2, al3, bh2, bh3);
                mma4(C[2*nt2+1], ah0, ah1, ah2, ah3, bl2, bl3);
            }
        }
        // stage C
        {
            int r0 = mrow + (lane >> 2);
            int c0 = (lane & 3) * 2;
#pragma unroll
            for (int nt = 0; nt < 16; nt++) {
                int col = nt * 8 + c0;
                *(float2*)(stage + r0 * 132 + col) = make_float2(C[nt][0], C[nt][1]);
                *(float2*)(stage + (r0 + 8) * 132 + col) = make_float2(C[nt][2], C[nt][3]);
            }
        }
        __syncthreads();

        for (int j = 0; j < 16; j++) {
            int el = wid * 16 + j;
            int e = e0 + el;
            if (e >= E) break;
            int rcv = rcv_s[el], snd = snd_s[el];
            float4 hv = h4g[(size_t)snd * 32 + lane];
            float4 rv = *(const float4*)(stage + el * 132 + lane * 4);
            const float ia = 0.0625f;
            float cx = hv.x * rv.x * ia, cy = hv.y * rv.y * ia;
            float cz = hv.z * rv.z * ia, cw = hv.w * rv.w * ia;
            float* bp = g_agg + (size_t)rcv * CC + lane * 4;
            if (l == 0) {
                red4(bp, cx, cy, cz, cw);
            } else if (l == 1) {
                float y0 = Ys[el*8], y1 = Ys[el*8+1], y2 = Ys[el*8+2];
                red4(bp + 1*NC, cx*y0, cy*y0, cz*y0, cw*y0);
                red4(bp + 2*NC, cx*y1, cy*y1, cz*y1, cw*y1);
                red4(bp + 3*NC, cx*y2, cy*y2, cz*y2, cw*y2);
            } else {
#pragma unroll
                for (int m = 0; m < 5; m++) {
                    float y = Ys[el*8 + 3 + m];
                    red4(bp + (4+m)*NC, cx*y, cy*y, cz*y, cw*y);
                }
            }
        }
        __syncthreads();
    }
}

// ---------------- SIMT fp32 GEMM (small tails) ----------------------------------
template<int ACT>
__global__ void __launch_bounds__(256)
gemm_k(const float* __restrict__ A, const float* __restrict__ B,
       float* __restrict__ C, int M, int N, int K, const float* __restrict__ bias)
{
    __shared__ float As[16][68];
    __shared__ float Bs[16][64];
    int tid = threadIdx.x;
    int tx = tid & 15, ty = tid >> 4;
    int bm = blockIdx.y * 64, bn = blockIdx.x * 64;
    float acc[4][4];
#pragma unroll
    for (int i = 0; i < 4; i++)
#pragma unroll
        for (int j = 0; j < 4; j++) acc[i][j] = 0.f;
    int mi = tid >> 2, kq = tid & 3;
    bool mvalid = (bm + mi) < M;
    const float* Arow = A + (size_t)(bm + mi) * K;
    for (int k0 = 0; k0 < K; k0 += 16) {
        float4 av = make_float4(0.f, 0.f, 0.f, 0.f);
        if (mvalid) av = *(const float4*)(Arow + k0 + kq * 4);
        As[kq*4+0][mi] = av.x; As[kq*4+1][mi] = av.y;
        As[kq*4+2][mi] = av.z; As[kq*4+3][mi] = av.w;
#pragma unroll
        for (int l = 0; l < 4; l++) {
            int idx = tid + l * 256;
            int ki = idx >> 6, ni = idx & 63;
            int n = bn + ni;
            Bs[ki][ni] = (n < N) ? B[(size_t)(k0 + ki) * N + n] : 0.f;
        }
        __syncthreads();
#pragma unroll
        for (int kk = 0; kk < 16; kk++) {
            float4 a4 = *(const float4*)(&As[kk][ty * 4]);
            float4 b4 = *(const float4*)(&Bs[kk][tx * 4]);
            float a[4] = {a4.x, a4.y, a4.z, a4.w};
            float b[4] = {b4.x, b4.y, b4.z, b4.w};
#pragma unroll
            for (int i = 0; i < 4; i++)
#pragma unroll
                for (int j = 0; j < 4; j++)
                    acc[i][j] = fmaf(a[i], b[j], acc[i][j]);
        }
        __syncthreads();
    }
#pragma unroll
    for (int i = 0; i < 4; i++) {
        int m = bm + ty * 4 + i;
        if (m >= M) continue;
#pragma unroll
        for (int j = 0; j < 4; j++) {
            int n = bn + tx * 4 + j;
            if (n >= N) continue;
            float v = acc[i][j];
            if (bias) v += bias[n];
            if (ACT) v = v / (1.f + __expf(-v));
            C[(size_t)m * N + n] = v;
        }
    }
}

// ---------------- symmetric contraction ----------------------------------------
__global__ void contract_k(const float* __restrict__ w0, const float* __restrict__ w1, int N)
{
    int i = blockIdx.x * blockDim.x + threadIdx.x;
    int NC = N * CC;
    if (i >= NC) return;
    int c = i & (CC - 1);
    const float* svt = g_svt;
    float* Bv = g_B;

    float s  = svt[i];
    float vx = svt[NC + i], vy = svt[2*NC + i], vz = svt[3*NC + i];
    float ta = svt[4*NC + i], tb = svt[5*NC + i], tcm = svt[6*NC + i];
    float td = svt[7*NC + i], te = svt[8*NC + i];

    float c3 = tcm * 0.5773502691896258f;
    float Txx = te - c3, Txy = ta, Txz = td;
    float Tyy = -te - c3, Tyz = tb;
    float Tzz = 2.f * c3;

    float v2 = vx*vx + vy*vy + vz*vz;
    float t2 = ta*ta + tb*tb + tcm*tcm + td*td + te*te;
    float Tvx = Txx*vx + Txy*vy + Txz*vz;
    float Tvy = Txy*vx + Tyy*vy + Tyz*vz;
    float Tvz = Txz*vx + Tyz*vy + Tzz*vz;
    float vTv = vx*Tvx + vy*Tvy + vz*Tvz;

    float B0 = w0[c]*s + w0[CC+c]*s*s + w0[2*CC+c]*v2 + w0[3*CC+c]*t2
             + w0[4*CC+c]*s*s*s + w0[5*CC+c]*s*v2 + w0[6*CC+c]*s*t2 + w0[7*CC+c]*vTv;

    float k0 = w1[c], k1 = w1[CC+c], k2 = w1[2*CC+c];
    float k3 = w1[3*CC+c], k4 = w1[4*CC+c], k5 = w1[5*CC+c];
    float f = k0 + k1*s + k3*s*s + k4*v2;
    float gT = k2 + k5*s;

    Bv[i] = B0;
    Bv[NC + i]   = f*vx + gT*Tvx;
    Bv[2*NC + i] = f*vy + gT*Tvy;
    Bv[3*NC + i] = f*vz + gT*Tvz;
}

// ---------------- finalize ------------------------------------------------------
__global__ void final_k(const float* __restrict__ W3, const float* __restrict__ wv,
                        float* __restrict__ out, int N)
{
    int lane = threadIdx.x & 31;
    int node = (blockIdx.x * blockDim.x + threadIdx.x) >> 5;
    if (node >= N) return;
    int NC = N * CC;
    const float* zr = g_zr;
    const float* h0 = g_hout;
    const float* h1 = g_hout + NC;

    float gate = zr[node*64 + lane] * W3[lane] + zr[node*64 + 32 + lane] * W3[32 + lane];
    float sx = 0.f, sy = 0.f, sz = 0.f;
#pragma unroll
    for (int c = lane; c < CC; c += 32) {
        float w = wv[c];
        sx = fmaf(h1[node*CC + c], w, sx);
        sy = fmaf(h1[NC + node*CC + c], w, sy);
        sz = fmaf(h1[2*NC + node*CC + c], w, sz);
    }
#pragma unroll
    for (int off = 16; off; off >>= 1) {
        gate += __shfl_xor_sync(0xffffffffu, gate, off);
        sx += __shfl_xor_sync(0xffffffffu, sx, off);
        sy += __shfl_xor_sync(0xffffffffu, sy, off);
        sz += __shfl_xor_sync(0xffffffffu, sz, off);
    }
    if (lane == 0) {
        float* ov = out + (size_t)N * 128 + (size_t)node * 3;
        ov[0] = sx * gate; ov[1] = sy * gate; ov[2] = sz * gate;
    }
    float* nf = out + (size_t)N * 131 + (size_t)node * 512;
#pragma unroll
    for (int c = lane; c < CC; c += 32) {
        nf[c] = h0[node*CC + c];
        nf[128 + 3*c + 0] = h1[node*CC + c];
        nf[128 + 3*c + 1] = h1[NC + node*CC + c];
        nf[128 + 3*c + 2] = h1[2*NC + node*CC + c];
    }
}

// ---------------- host launcher --------------------------------------------------
extern "C" void kernel_launch(void* const* d_in, const int* in_sizes, int n_in,
                              void* d_out, int out_size)
{
    const float* vectors    = (const float*)d_in[0];
    const float* lengths    = (const float*)d_in[1];
    const float* node_feats = (const float*)d_in[2];
    const float* edge_feats = (const float*)d_in[3];
    const int*   edge_index = (const int*)  d_in[4];
    const float* W_up = (const float*)d_in[5];
    const float* Wr1  = (const float*)d_in[6];
    const float* br1  = (const float*)d_in[7];
    const float* Wr2  = (const float*)d_in[8];
    const float* Wl0  = (const float*)d_in[9];
    const float* Wl1  = (const float*)d_in[10];
    const float* Wl2  = (const float*)d_in[11];
    const float* w0   = (const float*)d_in[12];
    const float* w1   = (const float*)d_in[13];
    const float* P0   = (const float*)d_in[14];
    const float* P1   = (const float*)d_in[15];
    const float* W1   = (const float*)d_in[16];
    const float* b1   = (const float*)d_in[17];
    const float* W2   = (const float*)d_in[18];
    const float* W3   = (const float*)d_in[19];
    const float* wv   = (const float*)d_in[20];
    float* out = (float*)d_out;

    int E = in_sizes[1];
    int N = in_sizes[2] / CC;
    int NC = N * CC;

    float *p_h, *p_agg, *p_svt, *p_B, *p_hout, *p_zr;
    __half *p_wt, *p_wr1t, *p_wr2t;
    cudaGetSymbolAddress((void**)&p_h,    g_h);
    cudaGetSymbolAddress((void**)&p_agg,  g_agg);
    cudaGetSymbolAddress((void**)&p_svt,  g_svt);
    cudaGetSymbolAddress((void**)&p_B,    g_B);
    cudaGetSymbolAddress((void**)&p_hout, g_hout);
    cudaGetSymbolAddress((void**)&p_zr,   g_zr);
    cudaGetSymbolAddress((void**)&p_wt,   g_wt);
    cudaGetSymbolAddress((void**)&p_wr1t, g_wr1t);
    cudaGetSymbolAddress((void**)&p_wr2t, g_wr2t);

    // weight prep: [n][k] hi/lo, padded strides
    const int TS = 2 * 128 * 136;
    prep_w<<<64, 256>>>(W_up, p_wt,          128, 128, 128, 136);
    prep_w<<<64, 256>>>(Wl0,  p_wt + 1*TS,   128, 128, 128, 136);
    prep_w<<<64, 256>>>(Wl1,  p_wt + 2*TS,   128, 128, 128, 136);
    prep_w<<<64, 256>>>(Wl2,  p_wt + 3*TS,   128, 128, 128, 136);
    prep_w<<<64, 256>>>(P0,   p_wt + 4*TS,   128, 128, 128, 136);
    prep_w<<<64, 256>>>(P1,   p_wt + 5*TS,   128, 128, 128, 136);
    prep_w<<<32, 256>>>(Wr1,  p_wr1t,        128,  64,  64, 136);
    prep_w<<<96, 256>>>(Wr2,  p_wr2t,         64, 384, 384,  72);

    int n4 = 9 * NC / 4;
    zero_agg_k<<<(n4 + 255) / 256, 256>>>(n4);

    int mt = (N + 127) / 128;
    const int SM_G = 139264;       // mma128 smem bytes
    const int SM_R = 104448 + 512; // mma_radial
    const int SM_E = 220160;       // edge
    cudaFuncSetAttribute(mma128, cudaFuncAttributeMaxDynamicSharedMemorySize, SM_G);
    cudaFuncSetAttribute(mma_radial, cudaFuncAttributeMaxDynamicSharedMemorySize, SM_R);
    cudaFuncSetAttribute(edge_mma, cudaFuncAttributeMaxDynamicSharedMemorySize, SM_E);

    // h = nf @ W_up
    mma128<<<dim3(mt, 1), 256, SM_G>>>(node_feats, p_h, N, 0);

    // z = silu(ef@Wr1 + len*wl + b) -> f16 hi/lo
    mma_radial<<<(E + 127) / 128, 256, SM_R>>>(edge_feats, lengths, Wr1 + 128*64, br1, E);

    // edge: R = z@Wr2 (mma) + vector-reduction scatter
    edge_mma<<<(E + 127) / 128, 256, SM_E>>>(vectors, edge_index, E, N);

    // svt = agg @ Wl (9 comps)
    mma128<<<dim3(mt, 9), 256, SM_G>>>(p_agg, p_svt, N, 1);

    contract_k<<<(NC + 255) / 256, 256>>>(w0, w1, N);

    // hout = B @ P (4 comps)
    mma128<<<dim3(mt, 4), 256, SM_G>>>(p_B, p_hout, N, 2);

    // zr = silu(h0@W1 + b1); scal = zr@W2 -> out
    gemm_k<1><<<dim3(1, (N + 63) / 64), 256>>>(p_hout, W1, p_zr, N, 64, 128, b1);
    gemm_k<0><<<dim3(2, (N + 63) / 64), 256>>>(p_zr, W2, out, N, 128, 64, nullptr);

    final_k<<<(N * 32 + 255) / 256, 256>>>(W3, wv, out, N);
}

// round 5
// speedup vs baseline: 1.2065x; 1.0863x over previous
#include <cuda_runtime.h>
#include <cuda_fp16.h>
#include <math.h>
#include <stdint.h>

#define NN 10000
#define EE 160000
#define CC 128

// ---------------- scratch ------------------------------------------------------
__device__ float  g_h   [NN*CC];
__device__ float  g_agg [9*NN*CC];
__device__ float  g_svt [9*NN*CC];
__device__ float  g_B   [4*NN*CC];
__device__ float  g_hout[4*NN*CC];          // h0, h1x, h1y, h1z
__device__ float  g_zr  [NN*64];
// prepped weights: f16 hi then lo, [n][k] rows padded
__device__ __half g_wt  [6*2*128*136];      // W_up, Wl0, Wl1, Wl2, P0, P1 (stride 136)
__device__ __half g_wr1t[2*64*136];         // Wr1^T (stride 136)
__device__ __half g_wr2t[2*384*72];         // Wr2^T (stride 72)

// ---------------- helpers -------------------------------------------------------
__device__ __forceinline__ uint32_t s2u(const void* p) {
    uint32_t a;
    asm("{ .reg .u64 t; cvta.to.shared.u64 t, %1; cvt.u32.u64 %0, t; }" : "=r"(a) : "l"(p));
    return a;
}
__device__ __forceinline__ void ldmx4(uint32_t& r0, uint32_t& r1, uint32_t& r2, uint32_t& r3,
                                      uint32_t a) {
    asm volatile("ldmatrix.sync.aligned.m8n8.x4.shared.b16 {%0,%1,%2,%3}, [%4];"
                 : "=r"(r0), "=r"(r1), "=r"(r2), "=r"(r3) : "r"(a));
}
__device__ __forceinline__ void mma4(float c[4], uint32_t a0, uint32_t a1, uint32_t a2,
                                     uint32_t a3, uint32_t b0, uint32_t b1) {
    asm volatile("mma.sync.aligned.m16n8k16.row.col.f32.f16.f16.f32 "
                 "{%0,%1,%2,%3},{%4,%5,%6,%7},{%8,%9},{%0,%1,%2,%3};"
                 : "+f"(c[0]), "+f"(c[1]), "+f"(c[2]), "+f"(c[3])
                 : "r"(a0), "r"(a1), "r"(a2), "r"(a3), "r"(b0), "r"(b1));
}
__device__ __forceinline__ uint32_t afa(uint32_t base, int lane, int mrow, int kb, int sh) {
    int row = mrow + (lane & 15);
    int k = kb + ((lane >> 4) << 3);
    return base + (uint32_t)(row * sh + k) * 2;
}
__device__ __forceinline__ uint32_t bfa(uint32_t base, int lane, int nb, int kb, int sh) {
    int n = nb + (lane & 7) + ((lane >> 4) << 3);
    int k = kb + (((lane >> 3) & 1) << 3);
    return base + (uint32_t)(n * sh + k) * 2;
}
__device__ __forceinline__ void red4(float* p, float a, float b, float c, float d) {
    asm volatile("red.global.add.v4.f32 [%0], {%1,%2,%3,%4};"
                 :: "l"(p), "f"(a), "f"(b), "f"(c), "f"(d) : "memory");
}
// interleaved 6-mma for a pair of accumulators (2 independent chains)
__device__ __forceinline__ void mma_pair(float Ce[4], float Co[4],
    uint32_t ah0,uint32_t ah1,uint32_t ah2,uint32_t ah3,
    uint32_t al0,uint32_t al1,uint32_t al2,uint32_t al3,
    uint32_t bh0,uint32_t bh1,uint32_t bh2,uint32_t bh3,
    uint32_t bl0,uint32_t bl1,uint32_t bl2,uint32_t bl3)
{
    mma4(Ce, ah0, ah1, ah2, ah3, bh0, bh1);
    mma4(Co, ah0, ah1, ah2, ah3, bh2, bh3);
    mma4(Ce, al0, al1, al2, al3, bh0, bh1);
    mma4(Co, al0, al1, al2, al3, bh2, bh3);
    mma4(Ce, ah0, ah1, ah2, ah3, bl0, bl1);
    mma4(Co, ah0, ah1, ah2, ah3, bl2, bl3);
}

// ---------------- merged weight prep (ONE launch) --------------------------------
__global__ void prep_all(const float* W_up, const float* Wl0, const float* Wl1,
                         const float* Wl2, const float* P0, const float* P1,
                         const float* Wr1, const float* Wr2)
{
    int w = blockIdx.y;
    const float* src; __half* dst; int K, Nr, ldw, stride;
    const int TS = 2 * 128 * 136;
    switch (w) {
        case 0: src = W_up; dst = g_wt;        K=128; Nr=128; ldw=128; stride=136; break;
        case 1: src = Wl0;  dst = g_wt + 1*TS; K=128; Nr=128; ldw=128; stride=136; break;
        case 2: src = Wl1;  dst = g_wt + 2*TS; K=128; Nr=128; ldw=128; stride=136; break;
        case 3: src = Wl2;  dst = g_wt + 3*TS; K=128; Nr=128; ldw=128; stride=136; break;
        case 4: src = P0;   dst = g_wt + 4*TS; K=128; Nr=128; ldw=128; stride=136; break;
        case 5: src = P1;   dst = g_wt + 5*TS; K=128; Nr=128; ldw=128; stride=136; break;
        case 6: src = Wr1;  dst = g_wr1t;      K=128; Nr= 64; ldw= 64; stride=136; break;
        default:src = Wr2;  dst = g_wr2t;      K= 64; Nr=384; ldw=384; stride= 72; break;
    }
    int i = blockIdx.x * blockDim.x + threadIdx.x;
    if (i >= K * Nr) return;
    int n = i / K, k = i % K;
    float v = src[(size_t)k * ldw + n];
    __half h = __float2half_rn(v);
    dst[(size_t)n * stride + k] = h;
    dst[(size_t)Nr * stride + (size_t)n * stride + k] = __float2half_rn(v - __half2float(h));
}

__global__ void zero_agg_k(int n4) {
    int i = blockIdx.x * blockDim.x + threadIdx.x;
    if (i < n4) ((float4*)g_agg)[i] = make_float4(0.f, 0.f, 0.f, 0.f);
}

__global__ void dummy_k() { if (threadIdx.x == 0) g_zr[0] = 0.f; }

// A-tile convert: fp32 row -> hi/lo f16 in smem (stride 136)
__device__ __forceinline__ void cvt_row(__half* Ah, __half* Al, int r, int half64,
                                        const float* Arow, bool valid) {
    int cb = half64 * 64;
#pragma unroll
    for (int q = 0; q < 16; q++) {
        float4 v = valid ? ((const float4*)Arow)[half64 * 16 + q]
                         : make_float4(0.f, 0.f, 0.f, 0.f);
        int idx = r * 136 + cb + q * 4;
        __half h0 = __float2half_rn(v.x), h1 = __float2half_rn(v.y);
        __half h2 = __float2half_rn(v.z), h3 = __float2half_rn(v.w);
        ((__half2*)(Ah + idx))[0] = __halves2half2(h0, h1);
        ((__half2*)(Ah + idx))[1] = __halves2half2(h2, h3);
        ((__half2*)(Al + idx))[0] = __halves2half2(__float2half_rn(v.x - __half2float(h0)),
                                                   __float2half_rn(v.y - __half2float(h1)));
        ((__half2*)(Al + idx))[1] = __halves2half2(__float2half_rn(v.z - __half2float(h2)),
                                                   __float2half_rn(v.w - __half2float(h3)));
    }
}

// ---------------- node GEMM (persistent B, tile loop) ----------------------------
// smem: Ah(0) Al(17408) Bh(34816) Bl(52224) halves; 139264 B
__global__ void __launch_bounds__(256)
mma128(const float* __restrict__ A0, float* __restrict__ O0, int M, int phase, int mt)
{
    extern __shared__ __half sh[];
    __half* Ah = sh;  __half* Al = sh + 17408;
    __half* Bh = sh + 34816;
    uint32_t sb = s2u(sh);
    int tid = threadIdx.x, wid = tid >> 5, lane = tid & 31;
    int comp = blockIdx.y;
    int tile;
    if (phase == 0) tile = 0;
    else if (phase == 1) tile = (comp == 0) ? 1 : (comp < 4 ? 2 : 3);
    else tile = (comp == 0) ? 4 : 5;
    const float* A = A0 + (size_t)comp * M * 128;
    float* O = O0 + (size_t)comp * M * 128;

    {   // B copy once: 4352 uint4
        const uint4* s = (const uint4*)(g_wt + (size_t)tile * (2*128*136));
        uint4* d = (uint4*)Bh;
        for (int i = tid; i < 4352; i += 256) d[i] = s[i];
    }
    uint32_t ab_h = sb, ab_l = sb + 17408*2, bb_h = sb + 34816*2, bb_l = sb + 52224*2;
    int mrow = wid * 16;
    int rr = tid >> 1, hf = tid & 1;

    for (int tl = blockIdx.x; tl < mt; tl += gridDim.x) {
        int bm = tl * 128;
        cvt_row(Ah, Al, rr, hf, A + (size_t)(bm + rr) * 128, (bm + rr) < M);
        __syncthreads();

        float C[16][4];
#pragma unroll
        for (int i = 0; i < 16; i++)
#pragma unroll
            for (int j = 0; j < 4; j++) C[i][j] = 0.f;

        for (int kb = 0; kb < 128; kb += 16) {
            uint32_t ah0, ah1, ah2, ah3, al0, al1, al2, al3;
            ldmx4(ah0, ah1, ah2, ah3, afa(ab_h, lane, mrow, kb, 136));
            ldmx4(al0, al1, al2, al3, afa(ab_l, lane, mrow, kb, 136));
#pragma unroll
            for (int nt2 = 0; nt2 < 8; nt2++) {
                uint32_t bh0, bh1, bh2, bh3, bl0, bl1, bl2, bl3;
                ldmx4(bh0, bh1, bh2, bh3, bfa(bb_h, lane, nt2 * 16, kb, 136));
                ldmx4(bl0, bl1, bl2, bl3, bfa(bb_l, lane, nt2 * 16, kb, 136));
                mma_pair(C[2*nt2], C[2*nt2+1], ah0,ah1,ah2,ah3, al0,al1,al2,al3,
                         bh0,bh1,bh2,bh3, bl0,bl1,bl2,bl3);
            }
        }

        int r0 = bm + mrow + (lane >> 2);
        int c0 = (lane & 3) * 2;
        bool v0 = r0 < M, v1 = (r0 + 8) < M;
#pragma unroll
        for (int nt = 0; nt < 16; nt++) {
            int col = nt * 8 + c0;
            if (v0) *(float2*)(O + (size_t)r0 * 128 + col) = make_float2(C[nt][0], C[nt][1]);
            if (v1) *(float2*)(O + (size_t)(r0 + 8) * 128 + col) = make_float2(C[nt][2], C[nt][3]);
        }
        __syncthreads();
    }
}

// ---------------- fused edge kernel ----------------------------------------------
// phase1 smem: efAh 0..34816, efAl ..69632, Wr1 hi/lo 69632..104448, wl/b 104448..104960
// phase2 smem: zh 0..18432, zl ..36864, Wr2 36864..147456, stage 147456..215040
// fixed:       Ys 215040..219136, snd 219136..219648, rcv ..220160
__global__ void __launch_bounds__(256)
edge_fused(const float* __restrict__ vectors, const int* __restrict__ edge_index,
           const float* __restrict__ edge_feats, const float* __restrict__ lengths,
           const float* __restrict__ wlast, const float* __restrict__ bias,
           int E, int N)
{
    extern __shared__ char smc[];
    uint32_t sb = s2u(smc);
    __half* efAh = (__half*)smc;
    __half* efAl = (__half*)(smc + 34816);
    float* wl_sm = (float*)(smc + 104448);
    float* b_sm  = (float*)(smc + 104704);
    float* stage = (float*)(smc + 147456);
    float* Ys    = (float*)(smc + 215040);
    int* snd_s   = (int*)(smc + 219136);
    int* rcv_s   = (int*)(smc + 219648);
    int tid = threadIdx.x, wid = tid >> 5, lane = tid & 31;
    int e0 = blockIdx.x * 128;
    int mrow = wid * 16;

    // ---- phase 1 fill ----
    if (tid < 64) { wl_sm[tid] = wlast[tid]; b_sm[tid] = bias[tid]; }
    {   // Wr1 hi/lo copy: 34816 B = 2176 uint4
        const uint4* s = (const uint4*)g_wr1t;
        uint4* d = (uint4*)(smc + 69632);
        for (int i = tid; i < 2176; i += 256) d[i] = s[i];
    }
    {   int r = tid >> 1, hf = tid & 1;
        cvt_row(efAh, efAl, r, hf, edge_feats + (size_t)(e0 + r) * 128, (e0 + r) < E);
    }
    if (tid < 128) {
        int e = e0 + tid;
        int snd = 0, rcv = 0;
        float vx = 0.f, vy = 1.f, vz = 0.f;
        if (e < E) {
            snd = edge_index[e]; rcv = edge_index[E + e];
            vx = vectors[3*e]; vy = vectors[3*e+1]; vz = vectors[3*e+2];
        }
        snd_s[tid] = snd; rcv_s[tid] = rcv;
        float inv = 1.f / (sqrtf(vx*vx + vy*vy + vz*vz) + 1e-9f);
        float ux = vx*inv, uy = vy*inv, uz = vz*inv;
        const float S3 = 1.7320508075688772f, S15 = 3.8729833462074170f;
        const float S15H = 1.9364916731037085f, S5H = 1.1180339887498949f;
        float* y = Ys + tid * 8;
        y[0] = S3*ux; y[1] = S3*uy; y[2] = S3*uz;
        y[3] = S15*ux*uy; y[4] = S15*uy*uz; y[5] = S5H*(3.f*uz*uz - 1.f);
        y[6] = S15*ux*uz; y[7] = S15H*(ux*ux - uy*uy);
    }
    __syncthreads();

    // ---- radial MMA: z = ef @ Wr1, M=128 N=64 K=128 ----
    float Cz[8][4];
#pragma unroll
    for (int i = 0; i < 8; i++)
#pragma unroll
        for (int j = 0; j < 4; j++) Cz[i][j] = 0.f;
    {
        uint32_t ab_h = sb, ab_l = sb + 34816, bb_h = sb + 69632, bb_l = sb + 87040;
        for (int kb = 0; kb < 128; kb += 16) {
            uint32_t ah0, ah1, ah2, ah3, al0, al1, al2, al3;
            ldmx4(ah0, ah1, ah2, ah3, afa(ab_h, lane, mrow, kb, 136));
            ldmx4(al0, al1, al2, al3, afa(ab_l, lane, mrow, kb, 136));
#pragma unroll
            for (int nt2 = 0; nt2 < 4; nt2++) {
                uint32_t bh0, bh1, bh2, bh3, bl0, bl1, bl2, bl3;
                ldmx4(bh0, bh1, bh2, bh3, bfa(bb_h, lane, nt2 * 16, kb, 136));
                ldmx4(bl0, bl1, bl2, bl3, bfa(bb_l, lane, nt2 * 16, kb, 136));
                mma_pair(Cz[2*nt2], Cz[2*nt2+1], ah0,ah1,ah2,ah3, al0,al1,al2,al3,
                         bh0,bh1,bh2,bh3, bl0,bl1,bl2,bl3);
            }
        }
    }
    __syncthreads();   // all reads of efA/Wr1 done

    // ---- epilogue: silu -> z hi/lo smem (stride 72 halves) ----
    {
        int r0 = mrow + (lane >> 2);
        int c0 = (lane & 3) * 2;
        float len0 = (e0 + r0     < E) ? lengths[e0 + r0]     : 0.f;
        float len1 = (e0 + r0 + 8 < E) ? lengths[e0 + r0 + 8] : 0.f;
#pragma unroll
        for (int nt = 0; nt < 8; nt++) {
            int col = nt * 8 + c0;
            float wl0 = wl_sm[col], wl1 = wl_sm[col + 1];
            float bb0 = b_sm[col],  bb1 = b_sm[col + 1];
            float f0 = Cz[nt][0] + len0 * wl0 + bb0;
            float f1 = Cz[nt][1] + len0 * wl1 + bb1;
            float f2 = Cz[nt][2] + len1 * wl0 + bb0;
            float f3 = Cz[nt][3] + len1 * wl1 + bb1;
            f0 = f0 / (1.f + __expf(-f0));
            f1 = f1 / (1.f + __expf(-f1));
            f2 = f2 / (1.f + __expf(-f2));
            f3 = f3 / (1.f + __expf(-f3));
            __half h0 = __float2half_rn(f0), h1 = __float2half_rn(f1);
            __half h2 = __float2half_rn(f2), h3 = __float2half_rn(f3);
            *(__half2*)(smc + r0 * 144 + col * 2) = __halves2half2(h0, h1);
            *(__half2*)(smc + (r0 + 8) * 144 + col * 2) = __halves2half2(h2, h3);
            *(__half2*)(smc + 18432 + r0 * 144 + col * 2) =
                __halves2half2(__float2half_rn(f0 - __half2float(h0)),
                               __float2half_rn(f1 - __half2float(h1)));
            *(__half2*)(smc + 18432 + (r0 + 8) * 144 + col * 2) =
                __halves2half2(__float2half_rn(f2 - __half2float(h2)),
                               __float2half_rn(f3 - __half2float(h3)));
        }
    }
    __syncthreads();   // z written; wl/b reads done

    {   // Wr2 copy: 110592 B = 6912 uint4
        const uint4* s = (const uint4*)g_wr2t;
        uint4* d = (uint4*)(smc + 36864);
        for (int i = tid; i < 6912; i += 256) d[i] = s[i];
    }
    __syncthreads();

    // ---- R = z @ Wr2 (3 chunks of 128 cols) + scatter ----
    uint32_t zb_h = sb, zb_l = sb + 18432;
    const float4* h4g = (const float4*)g_h;
    int NC = N * CC;

    for (int l = 0; l < 3; l++) {
        uint32_t wb_h = sb + 36864 + (uint32_t)l * 18432;
        uint32_t wb_l = sb + 92160 + (uint32_t)l * 18432;
        float C[16][4];
#pragma unroll
        for (int i = 0; i < 16; i++)
#pragma unroll
            for (int j = 0; j < 4; j++) C[i][j] = 0.f;

        for (int kb = 0; kb < 64; kb += 16) {
            uint32_t ah0, ah1, ah2, ah3, al0, al1, al2, al3;
            ldmx4(ah0, ah1, ah2, ah3, afa(zb_h, lane, mrow, kb, 72));
            ldmx4(al0, al1, al2, al3, afa(zb_l, lane, mrow, kb, 72));
#pragma unroll
            for (int nt2 = 0; nt2 < 8; nt2++) {
                uint32_t bh0, bh1, bh2, bh3, bl0, bl1, bl2, bl3;
                ldmx4(bh0, bh1, bh2, bh3, bfa(wb_h, lane, nt2 * 16, kb, 72));
                ldmx4(bl0, bl1, bl2, bl3, bfa(wb_l, lane, nt2 * 16, kb, 72));
                mma_pair(C[2*nt2], C[2*nt2+1], ah0,ah1,ah2,ah3, al0,al1,al2,al3,
                         bh0,bh1,bh2,bh3, bl0,bl1,bl2,bl3);
            }
        }
        {
            int r0 = mrow + (lane >> 2);
            int c0 = (lane & 3) * 2;
#pragma unroll
            for (int nt = 0; nt < 16; nt++) {
                int col = nt * 8 + c0;
                *(float2*)(stage + r0 * 132 + col) = make_float2(C[nt][0], C[nt][1]);
                *(float2*)(stage + (r0 + 8) * 132 + col) = make_float2(C[nt][2], C[nt][3]);
            }
        }
        __syncthreads();

        for (int j = 0; j < 16; j++) {
            int el = wid * 16 + j;
            int e = e0 + el;
            if (e >= E) break;
            int rcv = rcv_s[el], snd = snd_s[el];
            float4 hv = h4g[(size_t)snd * 32 + lane];
            float4 rv = *(const float4*)(stage + el * 132 + lane * 4);
            const float ia = 0.0625f;
            float cx = hv.x * rv.x * ia, cy = hv.y * rv.y * ia;
            float cz = hv.z * rv.z * ia, cw = hv.w * rv.w * ia;
            float* bp = g_agg + (size_t)rcv * CC + lane * 4;
            if (l == 0) {
                red4(bp, cx, cy, cz, cw);
            } else if (l == 1) {
                float y0 = Ys[el*8], y1 = Ys[el*8+1], y2 = Ys[el*8+2];
                red4(bp + 1*NC, cx*y0, cy*y0, cz*y0, cw*y0);
                red4(bp + 2*NC, cx*y1, cy*y1, cz*y1, cw*y1);
                red4(bp + 3*NC, cx*y2, cy*y2, cz*y2, cw*y2);
            } else {
#pragma unroll
                for (int m = 0; m < 5; m++) {
                    float y = Ys[el*8 + 3 + m];
                    red4(bp + (4+m)*NC, cx*y, cy*y, cz*y, cw*y);
                }
            }
        }
        __syncthreads();
    }
}

// ---------------- SIMT fp32 GEMM (small tails) ----------------------------------
template<int ACT>
__global__ void __launch_bounds__(256)
gemm_k(const float* __restrict__ A, const float* __restrict__ B,
       float* __restrict__ C, int M, int N, int K, const float* __restrict__ bias)
{
    __shared__ float As[16][68];
    __shared__ float Bs[16][64];
    int tid = threadIdx.x;
    int tx = tid & 15, ty = tid >> 4;
    int bm = blockIdx.y * 64, bn = blockIdx.x * 64;
    float acc[4][4];
#pragma unroll
    for (int i = 0; i < 4; i++)
#pragma unroll
        for (int j = 0; j < 4; j++) acc[i][j] = 0.f;
    int mi = tid >> 2, kq = tid & 3;
    bool mvalid = (bm + mi) < M;
    const float* Arow = A + (size_t)(bm + mi) * K;
    for (int k0 = 0; k0 < K; k0 += 16) {
        float4 av = make_float4(0.f, 0.f, 0.f, 0.f);
        if (mvalid) av = *(const float4*)(Arow + k0 + kq * 4);
        As[kq*4+0][mi] = av.x; As[kq*4+1][mi] = av.y;
        As[kq*4+2][mi] = av.z; As[kq*4+3][mi] = av.w;
#pragma unroll
        for (int l = 0; l < 4; l++) {
            int idx = tid + l * 256;
            int ki = idx >> 6, ni = idx & 63;
            int n = bn + ni;
            Bs[ki][ni] = (n < N) ? B[(size_t)(k0 + ki) * N + n] : 0.f;
        }
        __syncthreads();
#pragma unroll
        for (int kk = 0; kk < 16; kk++) {
            float4 a4 = *(const float4*)(&As[kk][ty * 4]);
            float4 b4 = *(const float4*)(&Bs[kk][tx * 4]);
            float a[4] = {a4.x, a4.y, a4.z, a4.w};
            float b[4] = {b4.x, b4.y, b4.z, b4.w};
#pragma unroll
            for (int i = 0; i < 4; i++)
#pragma unroll
                for (int j = 0; j < 4; j++)
                    acc[i][j] = fmaf(a[i], b[j], acc[i][j]);
        }
        __syncthreads();
    }
#pragma unroll
    for (int i = 0; i < 4; i++) {
        int m = bm + ty * 4 + i;
        if (m >= M) continue;
#pragma unroll
        for (int j = 0; j < 4; j++) {
            int n = bn + tx * 4 + j;
            if (n >= N) continue;
            float v = acc[i][j];
            if (bias) v += bias[n];
            if (ACT) v = v / (1.f + __expf(-v));
            C[(size_t)m * N + n] = v;
        }
    }
}

// ---------------- symmetric contraction ----------------------------------------
__global__ void contract_k(const float* __restrict__ w0, const float* __restrict__ w1, int N)
{
    int i = blockIdx.x * blockDim.x + threadIdx.x;
    int NC = N * CC;
    if (i >= NC) return;
    int c = i & (CC - 1);
    const float* svt = g_svt;
    float* Bv = g_B;

    float s  = svt[i];
    float vx = svt[NC + i], vy = svt[2*NC + i], vz = svt[3*NC + i];
    float ta = svt[4*NC + i], tb = svt[5*NC + i], tcm = svt[6*NC + i];
    float td = svt[7*NC + i], te = svt[8*NC + i];

    float c3 = tcm * 0.5773502691896258f;
    float Txx = te - c3, Txy = ta, Txz = td;
    float Tyy = -te - c3, Tyz = tb;
    float Tzz = 2.f * c3;

    float v2 = vx*vx + vy*vy + vz*vz;
    float t2 = ta*ta + tb*tb + tcm*tcm + td*td + te*te;
    float Tvx = Txx*vx + Txy*vy + Txz*vz;
    float Tvy = Txy*vx + Tyy*vy + Tyz*vz;
    float Tvz = Txz*vx + Tyz*vy + Tzz*vz;
    float vTv = vx*Tvx + vy*Tvy + vz*Tvz;

    float B0 = w0[c]*s + w0[CC+c]*s*s + w0[2*CC+c]*v2 + w0[3*CC+c]*t2
             + w0[4*CC+c]*s*s*s + w0[5*CC+c]*s*v2 + w0[6*CC+c]*s*t2 + w0[7*CC+c]*vTv;

    float k0 = w1[c], k1 = w1[CC+c], k2 = w1[2*CC+c];
    float k3 = w1[3*CC+c], k4 = w1[4*CC+c], k5 = w1[5*CC+c];
    float f = k0 + k1*s + k3*s*s + k4*v2;
    float gT = k2 + k5*s;

    Bv[i] = B0;
    Bv[NC + i]   = f*vx + gT*Tvx;
    Bv[2*NC + i] = f*vy + gT*Tvy;
    Bv[3*NC + i] = f*vz + gT*Tvz;
}

// ---------------- finalize ------------------------------------------------------
__global__ void final_k(const float* __restrict__ W3, const float* __restrict__ wv,
                        float* __restrict__ out, int N)
{
    int lane = threadIdx.x & 31;
    int node = (blockIdx.x * blockDim.x + threadIdx.x) >> 5;
    if (node >= N) return;
    int NC = N * CC;
    const float* zr = g_zr;
    const float* h0 = g_hout;
    const float* h1 = g_hout + NC;

    float gate = zr[node*64 + lane] * W3[lane] + zr[node*64 + 32 + lane] * W3[32 + lane];
    float sx = 0.f, sy = 0.f, sz = 0.f;
#pragma unroll
    for (int c = lane; c < CC; c += 32) {
        float w = wv[c];
        sx = fmaf(h1[node*CC + c], w, sx);
        sy = fmaf(h1[NC + node*CC + c], w, sy);
        sz = fmaf(h1[2*NC + node*CC + c], w, sz);
    }
#pragma unroll
    for (int off = 16; off; off >>= 1) {
        gate += __shfl_xor_sync(0xffffffffu, gate, off);
        sx += __shfl_xor_sync(0xffffffffu, sx, off);
        sy += __shfl_xor_sync(0xffffffffu, sy, off);
        sz += __shfl_xor_sync(0xffffffffu, sz, off);
    }
    if (lane == 0) {
        float* ov = out + (size_t)N * 128 + (size_t)node * 3;
        ov[0] = sx * gate; ov[1] = sy * gate; ov[2] = sz * gate;
    }
    float* nf = out + (size_t)N * 131 + (size_t)node * 512;
#pragma unroll
    for (int c = lane; c < CC; c += 32) {
        nf[c] = h0[node*CC + c];
        nf[128 + 3*c + 0] = h1[node*CC + c];
        nf[128 + 3*c + 1] = h1[NC + node*CC + c];
        nf[128 + 3*c + 2] = h1[2*NC + node*CC + c];
    }
}

// ---------------- host launcher --------------------------------------------------
extern "C" void kernel_launch(void* const* d_in, const int* in_sizes, int n_in,
                              void* d_out, int out_size)
{
    const float* vectors    = (const float*)d_in[0];
    const float* lengths    = (const float*)d_in[1];
    const float* node_feats = (const float*)d_in[2];
    const float* edge_feats = (const float*)d_in[3];
    const int*   edge_index = (const int*)  d_in[4];
    const float* W_up = (const float*)d_in[5];
    const float* Wr1  = (const float*)d_in[6];
    const float* br1  = (const float*)d_in[7];
    const float* Wr2  = (const float*)d_in[8];
    const float* Wl0  = (const float*)d_in[9];
    const float* Wl1  = (const float*)d_in[10];
    const float* Wl2  = (const float*)d_in[11];
    const float* w0   = (const float*)d_in[12];
    const float* w1   = (const float*)d_in[13];
    const float* P0   = (const float*)d_in[14];
    const float* P1   = (const float*)d_in[15];
    const float* W1   = (const float*)d_in[16];
    const float* b1   = (const float*)d_in[17];
    const float* W2   = (const float*)d_in[18];
    const float* W3   = (const float*)d_in[19];
    const float* wv   = (const float*)d_in[20];
    float* out = (float*)d_out;

    int E = in_sizes[1];
    int N = in_sizes[2] / CC;
    int NC = N * CC;

    float *p_h, *p_agg, *p_svt, *p_B, *p_hout, *p_zr;
    cudaGetSymbolAddress((void**)&p_h,    g_h);
    cudaGetSymbolAddress((void**)&p_agg,  g_agg);
    cudaGetSymbolAddress((void**)&p_svt,  g_svt);
    cudaGetSymbolAddress((void**)&p_B,    g_B);
    cudaGetSymbolAddress((void**)&p_hout, g_hout);
    cudaGetSymbolAddress((void**)&p_zr,   g_zr);

    // launch 0: all weight prep in one kernel
    prep_all<<<dim3(96, 8), 256>>>(W_up, Wl0, Wl1, Wl2, P0, P1, Wr1, Wr2);

    // launch 1: zero scatter accumulators
    int n4 = 9 * NC / 4;
    zero_agg_k<<<(n4 + 255) / 256, 256>>>(n4);

    int mt = (N + 127) / 128;
    const int SM_G = 139264;
    const int SM_E = 220160;
    cudaFuncSetAttribute(mma128, cudaFuncAttributeMaxDynamicSharedMemorySize, SM_G);
    cudaFuncSetAttribute(edge_fused, cudaFuncAttributeMaxDynamicSharedMemorySize, SM_E);

    // launch 2: h = nf @ W_up
    mma128<<<dim3(mt, 1), 256, SM_G>>>(node_feats, p_h, N, 0, mt);

    // launches 3,4: pads so ncu (-s 5) captures edge_fused
    dummy_k<<<1, 32>>>();
    dummy_k<<<1, 32>>>();

    // launch 5: fused radial + R-MMA + scatter
    edge_fused<<<(E + 127) / 128, 256, SM_E>>>(vectors, edge_index, edge_feats, lengths,
                                               Wr1 + 128*64, br1, E, N);

    // launch 6: svt = agg @ Wl (9 comps, persistent B)
    mma128<<<dim3(16, 9), 256, SM_G>>>(p_agg, p_svt, N, 1, mt);

    // launch 7
    contract_k<<<(NC + 255) / 256, 256>>>(w0, w1, N);

    // launch 8: hout = B @ P (4 comps)
    mma128<<<dim3(37, 4), 256, SM_G>>>(p_B, p_hout, N, 2, mt);

    // launches 9,10: readout tails
    gemm_k<1><<<dim3(1, (N + 63) / 64), 256>>>(p_hout, W1, p_zr, N, 64, 128, b1);
    gemm_k<0><<<dim3(2, (N + 63) / 64), 256>>>(p_zr, W2, out, N, 128, 64, nullptr);

    // launch 11
    final_k<<<(N * 32 + 255) / 256, 256>>>(W3, wv, out, N);
}